// round 1
// baseline (speedup 1.0000x reference)
#include <cuda_runtime.h>
#include <stdint.h>

// Shapes are fixed by the problem: N = M = 100000, B = 32, NNZ = 3.2M.
// Scratch lives in device globals (no allocation allowed in kernel_launch).
#define BATCH 32
#define MAXN 100000
#define MAXM 100000

__device__ float g_xT[(size_t)MAXN * BATCH];  // (N, B)  x transposed
__device__ float g_yT[(size_t)MAXM * BATCH];  // (M, B)  accumulator, bias-initialized

// ---------------------------------------------------------------------------
// 1) Transpose x: (B, N) -> (N, B). Tiled 32x32 via shared memory.
// ---------------------------------------------------------------------------
__global__ void transpose_in_kernel(const float* __restrict__ x, int N) {
    __shared__ float tile[32][33];
    const int n0 = blockIdx.x * 32;
    const int tx = threadIdx.x;   // 0..31
    const int ty = threadIdx.y;   // 0..7
    #pragma unroll
    for (int i = 0; i < 32; i += 8) {
        int b = ty + i;
        int n = n0 + tx;
        tile[b][tx] = (n < N) ? x[(size_t)b * N + n] : 0.0f;
    }
    __syncthreads();
    #pragma unroll
    for (int i = 0; i < 32; i += 8) {
        int n = n0 + ty + i;
        if (n < N) g_xT[(size_t)n * BATCH + tx] = tile[tx][ty + i];
    }
}

// ---------------------------------------------------------------------------
// 2) Init yT with broadcast bias: yT[m][b] = bias[m]
// ---------------------------------------------------------------------------
__global__ void init_yT_kernel(const float* __restrict__ bias, int M) {
    int idx = blockIdx.x * blockDim.x + threadIdx.x;   // m*32 + b
    if (idx < M * BATCH) {
        g_yT[idx] = bias[idx >> 5];
    }
}

// ---------------------------------------------------------------------------
// 3) Edge scatter. One warp = 4 edges; each edge handled by an 8-lane group,
//    each lane owns a float4 (4 batches). xT row = one 128B coalesced line.
//    Scatter via vectorized red.global.add.v4.f32 (sm_90+): 8 16B-reductions
//    per edge instead of 32 scalar atomics.
// ---------------------------------------------------------------------------
__global__ void edge_kernel(const int* __restrict__ src,
                            const int* __restrict__ dst,
                            const float* __restrict__ val,
                            int nnz) {
    const int warp = (blockIdx.x * blockDim.x + threadIdx.x) >> 5;
    const int lane = threadIdx.x & 31;
    const int g    = lane >> 3;    // edge group within warp (0..3)
    const int sub  = lane & 7;     // float4 slot within edge (0..7)

    const int e = warp * 4 + g;
    if (e >= nnz) return;

    const int   s = __ldg(src + e);
    const int   d = __ldg(dst + e);
    const float v = __ldg(val + e);

    const float4 xv = *reinterpret_cast<const float4*>(
        g_xT + (size_t)s * BATCH + sub * 4);

    const float cx = v * xv.x;
    const float cy = v * xv.y;
    const float cz = v * xv.z;
    const float cw = v * xv.w;

    float* p = g_yT + (size_t)d * BATCH + sub * 4;
    asm volatile("red.global.add.v4.f32 [%0], {%1, %2, %3, %4};"
                 :: "l"(p), "f"(cx), "f"(cy), "f"(cz), "f"(cw)
                 : "memory");
}

// ---------------------------------------------------------------------------
// 4) Transpose out: (M, B) -> (B, M). Tiled 32x32.
// ---------------------------------------------------------------------------
__global__ void transpose_out_kernel(float* __restrict__ out, int M) {
    __shared__ float tile[32][33];
    const int m0 = blockIdx.x * 32;
    const int tx = threadIdx.x;
    const int ty = threadIdx.y;
    #pragma unroll
    for (int i = 0; i < 32; i += 8) {
        int m = m0 + ty + i;
        if (m < M) tile[ty + i][tx] = g_yT[(size_t)m * BATCH + tx];
    }
    __syncthreads();
    #pragma unroll
    for (int i = 0; i < 32; i += 8) {
        int b = ty + i;
        int m = m0 + tx;
        if (m < M) out[(size_t)b * M + m] = tile[tx][b];
    }
}

// ---------------------------------------------------------------------------
// kernel_launch
// Inputs (metadata order): x (B*N f32), indices (2*NNZ i32), values (NNZ f32),
// bias (M f32). Output: (B, M) f32.
// ---------------------------------------------------------------------------
extern "C" void kernel_launch(void* const* d_in, const int* in_sizes, int n_in,
                              void* d_out, int out_size) {
    const float* x       = (const float*)d_in[0];
    const int*   indices = (const int*)  d_in[1];
    const float* values  = (const float*)d_in[2];
    const float* bias    = (const float*)d_in[3];
    float*       out     = (float*)d_out;

    const int N   = in_sizes[0] / BATCH;
    const int nnz = in_sizes[1] / 2;
    const int M   = in_sizes[3];

    const int* src = indices;         // indices[0, :]
    const int* dst = indices + nnz;   // indices[1, :]

    dim3 tb(32, 8);

    transpose_in_kernel<<<(N + 31) / 32, tb>>>(x, N);

    init_yT_kernel<<<(M * BATCH + 255) / 256, 256>>>(bias, M);

    const int warps  = (nnz + 3) / 4;
    const int threads = warps * 32;
    edge_kernel<<<(threads + 255) / 256, 256>>>(src, dst, values, nnz);

    transpose_out_kernel<<<(M + 31) / 32, tb>>>(out, M);
}